// round 1
// baseline (speedup 1.0000x reference)
#include <cuda_runtime.h>
#include <cuda_bf16.h>
#include <math.h>

// ---------------- problem constants ----------------
#define BATCH   2
#define SEQL    2048
#define DMODEL  1024
#define DSTATE  16
#define DCONV   4
#define DINNER  2048            // EXPAND * DMODEL
#define NROWS   (BATCH * SEQL)  // 4096 flattened (b,l) rows

// ---------------- scratch (static device globals; no allocation) ----------------
__device__ float g_xz[NROWS * 2 * DINNER];   // [b,l, 4096]  (xa | z)
__device__ float g_xc[NROWS * DINNER];       // conv+silu output
__device__ float g_bc[NROWS * 32];           // [B_ssm(16) | C_ssm(16)]
__device__ float g_dt[NROWS * DINNER];       // delta (softplus)
__device__ float g_gg[NROWS * DINNER];       // (y + D*xc) * silu(z)

// ---------------- double-buffered SGEMM: C[M,N] = A[M,K] @ B[K,N] ----------------
// Requires M%128==0, N%128==0, K%8==0 (true for all uses here).
#define BM 128
#define BN 128
#define BK 8

__global__ __launch_bounds__(256, 2)
void sgemm_kernel(const float* __restrict__ A, const float* __restrict__ B,
                  float* __restrict__ C, int M, int N, int K)
{
    __shared__ float As[2][BK][BM];
    __shared__ float Bs[2][BK][BN];

    const int tid = threadIdx.x;
    const int bx = blockIdx.x;          // N tile
    const int by = blockIdx.y;          // M tile

    const float* Ab = A + (size_t)by * BM * K;
    const float* Bb = B + (size_t)bx * BN;

    // A-tile loader: 128 rows x 8 cols, each thread one float4
    const int arow  = tid >> 1;          // 0..127
    const int acol4 = (tid & 1) * 4;     // 0 or 4
    // B-tile loader: 8 rows x 128 cols, each thread one float4
    const int brow  = tid >> 5;          // 0..7
    const int bcol4 = (tid & 31) * 4;    // 0..124

    const int tx = tid & 15;             // 0..15 (N microtiles)
    const int ty = tid >> 4;             // 0..15 (M microtiles)

    float acc[8][8];
    #pragma unroll
    for (int i = 0; i < 8; i++)
        #pragma unroll
        for (int j = 0; j < 8; j++) acc[i][j] = 0.f;

    const int nk = K / BK;

    // prologue: stage 0
    {
        float4 av = *(const float4*)(Ab + (size_t)arow * K + acol4);
        As[0][acol4 + 0][arow] = av.x;
        As[0][acol4 + 1][arow] = av.y;
        As[0][acol4 + 2][arow] = av.z;
        As[0][acol4 + 3][arow] = av.w;
        float4 bv = *(const float4*)(Bb + (size_t)brow * N + bcol4);
        *(float4*)&Bs[0][brow][bcol4] = bv;
    }
    __syncthreads();

    for (int kt = 0; kt < nk; kt++) {
        const int cur = kt & 1;
        const int nxt = cur ^ 1;
        if (kt + 1 < nk) {
            const int k0 = (kt + 1) * BK;
            float4 av = *(const float4*)(Ab + (size_t)arow * K + k0 + acol4);
            As[nxt][acol4 + 0][arow] = av.x;
            As[nxt][acol4 + 1][arow] = av.y;
            As[nxt][acol4 + 2][arow] = av.z;
            As[nxt][acol4 + 3][arow] = av.w;
            float4 bv = *(const float4*)(Bb + ((size_t)k0 + brow) * N + bcol4);
            *(float4*)&Bs[nxt][brow][bcol4] = bv;
        }
        #pragma unroll
        for (int k = 0; k < BK; k++) {
            float a[8], b[8];
            float4 a0 = *(const float4*)&As[cur][k][ty * 8];
            float4 a1 = *(const float4*)&As[cur][k][ty * 8 + 4];
            a[0]=a0.x; a[1]=a0.y; a[2]=a0.z; a[3]=a0.w;
            a[4]=a1.x; a[5]=a1.y; a[6]=a1.z; a[7]=a1.w;
            float4 b0 = *(const float4*)&Bs[cur][k][tx * 8];
            float4 b1 = *(const float4*)&Bs[cur][k][tx * 8 + 4];
            b[0]=b0.x; b[1]=b0.y; b[2]=b0.z; b[3]=b0.w;
            b[4]=b1.x; b[5]=b1.y; b[6]=b1.z; b[7]=b1.w;
            #pragma unroll
            for (int i = 0; i < 8; i++)
                #pragma unroll
                for (int j = 0; j < 8; j++)
                    acc[i][j] = fmaf(a[i], b[j], acc[i][j]);
        }
        __syncthreads();
    }

    // epilogue: float4 stores
    #pragma unroll
    for (int i = 0; i < 8; i++) {
        const size_t row = (size_t)by * BM + ty * 8 + i;
        float* Cp = C + row * N + (size_t)bx * BN + tx * 8;
        float4 v0 = make_float4(acc[i][0], acc[i][1], acc[i][2], acc[i][3]);
        float4 v1 = make_float4(acc[i][4], acc[i][5], acc[i][6], acc[i][7]);
        *(float4*)(Cp)     = v0;
        *(float4*)(Cp + 4) = v1;
    }
}

// ---------------- depthwise causal conv (D_CONV=4) + bias + SiLU ----------------
__global__ void conv_silu_kernel(const float* __restrict__ xz,
                                 const float* __restrict__ cw,
                                 const float* __restrict__ cb,
                                 float* __restrict__ xc)
{
    int idx = blockIdx.x * blockDim.x + threadIdx.x;   // over NROWS*DINNER
    if (idx >= NROWS * DINNER) return;
    int d  = idx & (DINNER - 1);
    int bl = idx >> 11;                // /DINNER
    int l  = bl & (SEQL - 1);
    int b  = bl >> 11;                 // /SEQL

    float acc = cb[d];
    const float w0 = cw[d * 4 + 0], w1 = cw[d * 4 + 1],
                w2 = cw[d * 4 + 2], w3 = cw[d * 4 + 3];
    const float* base = xz + ((size_t)b * SEQL) * (2 * DINNER) + d;
    // xa is the first DINNER columns of xz
    if (l >= 3) acc = fmaf(w0, base[(size_t)(l - 3) * (2 * DINNER)], acc);
    if (l >= 2) acc = fmaf(w1, base[(size_t)(l - 2) * (2 * DINNER)], acc);
    if (l >= 1) acc = fmaf(w2, base[(size_t)(l - 1) * (2 * DINNER)], acc);
    acc = fmaf(w3, base[(size_t)l * (2 * DINNER)], acc);

    float sig = 1.f / (1.f + expf(-acc));
    xc[idx] = acc * sig;
}

// ---------------- BC = xc @ W_xproj  (N=32 skinny GEMM, one block per row) ------
__global__ void xproj_kernel(const float* __restrict__ xc,
                             const float* __restrict__ W,   // [DINNER, 32]
                             float* __restrict__ bc)
{
    const int r  = blockIdx.x;            // 0..NROWS-1
    const int c  = threadIdx.x & 31;      // output column
    const int st = threadIdx.x >> 5;      // stripe 0..7
    const float* xr = xc + (size_t)r * DINNER;

    float acc = 0.f;
    for (int k = st; k < DINNER; k += 8)
        acc = fmaf(xr[k], W[k * 32 + c], acc);

    __shared__ float red[8][32];
    red[st][c] = acc;
    __syncthreads();
    if (threadIdx.x < 32) {
        float s = 0.f;
        #pragma unroll
        for (int i = 0; i < 8; i++) s += red[i][threadIdx.x];
        bc[(size_t)r * 32 + threadIdx.x] = s;
    }
}

// ---------------- delta = softplus(B_ssm @ W_dt + b_dt) -------------------------
__global__ void delta_kernel(const float* __restrict__ bc,
                             const float* __restrict__ Wdt,  // [16, DINNER]
                             const float* __restrict__ bdt,
                             float* __restrict__ dt)
{
    int idx = blockIdx.x * blockDim.x + threadIdx.x;   // over NROWS*DINNER
    if (idx >= NROWS * DINNER) return;
    int d = idx & (DINNER - 1);
    int r = idx >> 11;
    const float* Br = bc + (size_t)r * 32;   // first 16 = B_ssm
    float acc = bdt[d];
    #pragma unroll
    for (int s = 0; s < DSTATE; s++)
        acc = fmaf(Br[s], Wdt[s * DINNER + d], acc);
    // softplus
    float sp = (acc > 20.f) ? acc : log1pf(expf(acc));
    dt[idx] = sp;
}

// ---------------- selective scan: 16 lanes per channel, fused gate --------------
// g[b,l,d] = (sum_s h[b,d,s]*C[b,l,s] + D[d]*xc[b,l,d]) * silu(z[b,l,d])
__global__ void scan_kernel(const float* __restrict__ xc,
                            const float* __restrict__ dt,
                            const float* __restrict__ bc,
                            const float* __restrict__ A_log,  // [DINNER,16]
                            const float* __restrict__ Dvec,
                            const float* __restrict__ xz,     // z at col 2048+d
                            float* __restrict__ g)
{
    int gid = blockIdx.x * blockDim.x + threadIdx.x;   // BATCH*DINNER*16 threads
    int s   = gid & 15;
    int ch  = gid >> 4;                 // 0..4095
    int d   = ch & (DINNER - 1);
    int b   = ch >> 11;

    const float a  = -expf(A_log[d * DSTATE + s]);
    const float Dd = Dvec[d];

    const float* dptr = dt + (size_t)b * SEQL * DINNER + d;
    const float* xptr = xc + (size_t)b * SEQL * DINNER + d;
    const float* zptr = xz + (size_t)b * SEQL * (2 * DINNER) + DINNER + d;
    const float* bcb  = bc + (size_t)b * SEQL * 32;
    float*       gptr = g  + (size_t)b * SEQL * DINNER + d;

    float h = 0.f;
    for (int l = 0; l < SEQL; l++) {
        float dtv = dptr[(size_t)l * DINNER];     // broadcast within 16-lane group
        float xt  = xptr[(size_t)l * DINNER];
        float Bt  = bcb[l * 32 + s];
        float Ct  = bcb[l * 32 + 16 + s];

        float dA = expf(dtv * a);
        h = fmaf(dA, h, dtv * xt * Bt);

        float p = h * Ct;
        p += __shfl_xor_sync(0xffffffffu, p, 8);
        p += __shfl_xor_sync(0xffffffffu, p, 4);
        p += __shfl_xor_sync(0xffffffffu, p, 2);
        p += __shfl_xor_sync(0xffffffffu, p, 1);

        if (s == 0) {
            float y   = fmaf(Dd, xt, p);
            float z   = zptr[(size_t)l * (2 * DINNER)];
            float sig = 1.f / (1.f + expf(-z));
            gptr[(size_t)l * DINNER] = y * (z * sig);
        }
    }
}

// ---------------- launch ----------------
extern "C" void kernel_launch(void* const* d_in, const int* in_sizes, int n_in,
                              void* d_out, int out_size)
{
    const float* x      = (const float*)d_in[0];   // [2,2048,1024]
    const float* W_in   = (const float*)d_in[1];   // [1024,4096]
    const float* conv_w = (const float*)d_in[2];   // [2048,4]
    const float* conv_b = (const float*)d_in[3];   // [2048]
    const float* W_xprj = (const float*)d_in[4];   // [2048,32]
    const float* W_dt   = (const float*)d_in[5];   // [16,2048]
    const float* b_dt   = (const float*)d_in[6];   // [2048]
    const float* A_log  = (const float*)d_in[7];   // [2048,16]
    const float* Dvec   = (const float*)d_in[8];   // [2048]
    const float* W_out  = (const float*)d_in[9];   // [2048,1024]
    float* out = (float*)d_out;                    // [2,2048,1024]

    float *xz, *xc, *bc, *dt, *gg;
    cudaGetSymbolAddress((void**)&xz, g_xz);
    cudaGetSymbolAddress((void**)&xc, g_xc);
    cudaGetSymbolAddress((void**)&bc, g_bc);
    cudaGetSymbolAddress((void**)&dt, g_dt);
    cudaGetSymbolAddress((void**)&gg, g_gg);

    // 1) xz = x @ W_in     (M=4096, K=1024, N=4096)
    {
        dim3 grid(2 * DINNER / BN, NROWS / BM);
        sgemm_kernel<<<grid, 256>>>(x, W_in, xz, NROWS, 2 * DINNER, DMODEL);
    }
    // 2) depthwise conv + SiLU
    {
        int total = NROWS * DINNER;
        conv_silu_kernel<<<(total + 255) / 256, 256>>>(xz, conv_w, conv_b, xc);
    }
    // 3) BC = xc @ W_xproj
    xproj_kernel<<<NROWS, 256>>>(xc, W_xprj, bc);
    // 4) delta = softplus(B @ W_dt + b_dt)
    {
        int total = NROWS * DINNER;
        delta_kernel<<<(total + 255) / 256, 256>>>(bc, W_dt, b_dt, dt);
    }
    // 5) selective scan + gate fusion
    {
        int total = BATCH * DINNER * DSTATE;   // 65536
        scan_kernel<<<total / 256, 256>>>(xc, dt, bc, A_log, Dvec, xz, gg);
    }
    // 6) out = g @ W_out   (M=4096, K=2048, N=1024)
    {
        dim3 grid(DMODEL / BN, NROWS / BM);
        sgemm_kernel<<<grid, 256>>>(gg, W_out, out, NROWS, DMODEL, DINNER);
    }
}

// round 2
// speedup vs baseline: 1.3798x; 1.3798x over previous
#include <cuda_runtime.h>
#include <cuda_bf16.h>
#include <math.h>
#include <stdint.h>

// ---------------- problem constants ----------------
#define BATCH   2
#define SEQL    2048
#define DMODEL  1024
#define DSTATE  16
#define DCONV   4
#define DINNER  2048            // EXPAND * DMODEL
#define NROWS   (BATCH * SEQL)  // 4096 flattened (b,l) rows

// ---------------- scratch (static device globals; no allocation) ----------------
__device__ float g_xz[NROWS * 2 * DINNER];   // [b,l, 4096]  (xa | z)
__device__ float g_xc[NROWS * DINNER];       // conv+silu output
__device__ float g_bc[NROWS * 32];           // [B_ssm(16) | C_ssm(16)]
__device__ float g_dt[NROWS * DINNER];       // delta (softplus)
__device__ float g_gg[NROWS * DINNER];       // (y + D*xc) * silu(z)

// =======================================================================
// TF32 tensor-core GEMM: C[M,N] = A[M,K] @ B[K,N], all row-major fp32.
// Block tile 128x128x16, 8 warps (4x2), warp tile 32x64, mma.m16n8k8.tf32.
// Requires M%128==0, N%128==0, K%16==0.
// =======================================================================
#define TBM 128
#define TBN 128
#define TBK 16
#define APAD 4     // row stride 20 floats: banks 20g+t conflict-free
#define BPAD 8     // row stride 136 floats: banks 8t+g conflict-free

__device__ __forceinline__ void cpasync16(void* dst, const void* src) {
    uint32_t d = (uint32_t)__cvta_generic_to_shared(dst);
    asm volatile("cp.async.cg.shared.global [%0], [%1], 16;\n" :: "r"(d), "l"(src));
}
__device__ __forceinline__ uint32_t f2tf32(float x) {
    uint32_t r;
    asm("cvt.rna.tf32.f32 %0, %1;" : "=r"(r) : "f"(x));
    return r;
}

__global__ __launch_bounds__(256)
void tf32gemm_kernel(const float* __restrict__ A, const float* __restrict__ B,
                     float* __restrict__ C, int M, int N, int K)
{
    __shared__ float As[2][TBM][TBK + APAD];
    __shared__ float Bs[2][TBK][TBN + BPAD];

    const int tid  = threadIdx.x;
    const int bx   = blockIdx.x;     // N tile
    const int by   = blockIdx.y;     // M tile
    const int warp = tid >> 5;
    const int lane = tid & 31;
    const int wm   = warp >> 1;      // 0..3
    const int wn   = warp & 1;       // 0..1
    const int g    = lane >> 2;      // groupID 0..7
    const int t    = lane & 3;       // threadID_in_group

    const float* Ab = A + (size_t)by * TBM * K;
    const float* Bb = B + (size_t)bx * TBN;

    float acc[2][8][4];
    #pragma unroll
    for (int i = 0; i < 2; i++)
        #pragma unroll
        for (int j = 0; j < 8; j++)
            #pragma unroll
            for (int v = 0; v < 4; v++) acc[i][j][v] = 0.f;

    // loader indices
    const int ar  = tid >> 2;          // A row 0..63 (and +64)
    const int ac4 = (tid & 3) * 4;     // A col 0/4/8/12
    const int br  = tid >> 5;          // B row 0..7 (and +8)
    const int bc4 = (tid & 31) * 4;    // B col

    const int nk = K / TBK;

    // ---- prologue: stage 0 ----
    {
        cpasync16(&As[0][ar][ac4],      Ab + (size_t)ar * K + ac4);
        cpasync16(&As[0][ar + 64][ac4], Ab + (size_t)(ar + 64) * K + ac4);
        cpasync16(&Bs[0][br][bc4],      Bb + (size_t)br * N + bc4);
        cpasync16(&Bs[0][br + 8][bc4],  Bb + (size_t)(br + 8) * N + bc4);
        asm volatile("cp.async.commit_group;\n" ::: "memory");
    }

    for (int kt = 0; kt < nk; kt++) {
        const int cur = kt & 1;
        if (kt + 1 < nk) {
            const int nxt = cur ^ 1;
            const int k0  = (kt + 1) * TBK;
            cpasync16(&As[nxt][ar][ac4],      Ab + (size_t)ar * K + k0 + ac4);
            cpasync16(&As[nxt][ar + 64][ac4], Ab + (size_t)(ar + 64) * K + k0 + ac4);
            cpasync16(&Bs[nxt][br][bc4],      Bb + (size_t)(k0 + br) * N + bc4);
            cpasync16(&Bs[nxt][br + 8][bc4],  Bb + (size_t)(k0 + br + 8) * N + bc4);
            asm volatile("cp.async.commit_group;\n" ::: "memory");
            asm volatile("cp.async.wait_group 1;\n" ::: "memory");
        } else {
            asm volatile("cp.async.wait_group 0;\n" ::: "memory");
        }
        __syncthreads();

        #pragma unroll
        for (int kk = 0; kk < TBK; kk += 8) {
            uint32_t af[2][4];
            uint32_t bf[8][2];
            #pragma unroll
            for (int mt = 0; mt < 2; mt++) {
                const int m0 = wm * 32 + mt * 16;
                af[mt][0] = f2tf32(As[cur][m0 + g][kk + t]);
                af[mt][1] = f2tf32(As[cur][m0 + g + 8][kk + t]);
                af[mt][2] = f2tf32(As[cur][m0 + g][kk + t + 4]);
                af[mt][3] = f2tf32(As[cur][m0 + g + 8][kk + t + 4]);
            }
            #pragma unroll
            for (int nt = 0; nt < 8; nt++) {
                const int n0 = wn * 64 + nt * 8 + g;
                bf[nt][0] = f2tf32(Bs[cur][kk + t][n0]);
                bf[nt][1] = f2tf32(Bs[cur][kk + t + 4][n0]);
            }
            #pragma unroll
            for (int mt = 0; mt < 2; mt++)
                #pragma unroll
                for (int nt = 0; nt < 8; nt++) {
                    float* c = acc[mt][nt];
                    asm volatile(
                        "mma.sync.aligned.m16n8k8.row.col.f32.tf32.tf32.f32 "
                        "{%0,%1,%2,%3}, {%4,%5,%6,%7}, {%8,%9}, {%0,%1,%2,%3};\n"
                        : "+f"(c[0]), "+f"(c[1]), "+f"(c[2]), "+f"(c[3])
                        : "r"(af[mt][0]), "r"(af[mt][1]), "r"(af[mt][2]), "r"(af[mt][3]),
                          "r"(bf[nt][0]), "r"(bf[nt][1]));
                }
        }
        __syncthreads();
    }

    // ---- epilogue ----
    const size_t rowBase = (size_t)by * TBM + wm * 32;
    const int    colBase = bx * TBN + wn * 64;
    #pragma unroll
    for (int mt = 0; mt < 2; mt++) {
        #pragma unroll
        for (int nt = 0; nt < 8; nt++) {
            const size_t row = rowBase + mt * 16 + g;
            const int    col = colBase + nt * 8 + 2 * t;
            float2 v01 = make_float2(acc[mt][nt][0], acc[mt][nt][1]);
            float2 v23 = make_float2(acc[mt][nt][2], acc[mt][nt][3]);
            *(float2*)(C + row * N + col)       = v01;
            *(float2*)(C + (row + 8) * N + col) = v23;
        }
    }
}

// ---------------- depthwise causal conv (D_CONV=4) + bias + SiLU ----------------
__global__ void conv_silu_kernel(const float* __restrict__ xz,
                                 const float* __restrict__ cw,
                                 const float* __restrict__ cb,
                                 float* __restrict__ xc)
{
    int idx = blockIdx.x * blockDim.x + threadIdx.x;   // over NROWS*DINNER
    if (idx >= NROWS * DINNER) return;
    int d  = idx & (DINNER - 1);
    int bl = idx >> 11;                // /DINNER
    int l  = bl & (SEQL - 1);
    int b  = bl >> 11;                 // /SEQL

    float acc = cb[d];
    const float w0 = cw[d * 4 + 0], w1 = cw[d * 4 + 1],
                w2 = cw[d * 4 + 2], w3 = cw[d * 4 + 3];
    const float* base = xz + ((size_t)b * SEQL) * (2 * DINNER) + d;
    if (l >= 3) acc = fmaf(w0, base[(size_t)(l - 3) * (2 * DINNER)], acc);
    if (l >= 2) acc = fmaf(w1, base[(size_t)(l - 2) * (2 * DINNER)], acc);
    if (l >= 1) acc = fmaf(w2, base[(size_t)(l - 1) * (2 * DINNER)], acc);
    acc = fmaf(w3, base[(size_t)l * (2 * DINNER)], acc);

    float sig = 1.f / (1.f + expf(-acc));
    xc[idx] = acc * sig;
}

// ---------------- BC = xc @ W_xproj  (N=32 skinny GEMM, one block per row) ------
__global__ void xproj_kernel(const float* __restrict__ xc,
                             const float* __restrict__ W,   // [DINNER, 32]
                             float* __restrict__ bc)
{
    const int r  = blockIdx.x;            // 0..NROWS-1
    const int c  = threadIdx.x & 31;      // output column
    const int st = threadIdx.x >> 5;      // stripe 0..7
    const float* xr = xc + (size_t)r * DINNER;

    float acc = 0.f;
    for (int k = st; k < DINNER; k += 8)
        acc = fmaf(xr[k], W[k * 32 + c], acc);

    __shared__ float red[8][32];
    red[st][c] = acc;
    __syncthreads();
    if (threadIdx.x < 32) {
        float s = 0.f;
        #pragma unroll
        for (int i = 0; i < 8; i++) s += red[i][threadIdx.x];
        bc[(size_t)r * 32 + threadIdx.x] = s;
    }
}

// ---------------- delta = softplus(B_ssm @ W_dt + b_dt) -------------------------
__global__ void delta_kernel(const float* __restrict__ bc,
                             const float* __restrict__ Wdt,  // [16, DINNER]
                             const float* __restrict__ bdt,
                             float* __restrict__ dt)
{
    int idx = blockIdx.x * blockDim.x + threadIdx.x;   // over NROWS*DINNER
    if (idx >= NROWS * DINNER) return;
    int d = idx & (DINNER - 1);
    int r = idx >> 11;
    const float* Br = bc + (size_t)r * 32;   // first 16 = B_ssm
    float acc = bdt[d];
    #pragma unroll
    for (int s = 0; s < DSTATE; s++)
        acc = fmaf(Br[s], Wdt[s * DINNER + d], acc);
    float sp = (acc > 20.f) ? acc : log1pf(expf(acc));
    dt[idx] = sp;
}

// ---------------- selective scan: 16 lanes per channel, fused gate --------------
__global__ void scan_kernel(const float* __restrict__ xc,
                            const float* __restrict__ dt,
                            const float* __restrict__ bc,
                            const float* __restrict__ A_log,  // [DINNER,16]
                            const float* __restrict__ Dvec,
                            const float* __restrict__ xz,     // z at col 2048+d
                            float* __restrict__ g)
{
    int gid = blockIdx.x * blockDim.x + threadIdx.x;   // BATCH*DINNER*16 threads
    int s   = gid & 15;
    int ch  = gid >> 4;                 // 0..4095
    int d   = ch & (DINNER - 1);
    int b   = ch >> 11;

    const float a  = -expf(A_log[d * DSTATE + s]);
    const float Dd = Dvec[d];

    const float* dptr = dt + (size_t)b * SEQL * DINNER + d;
    const float* xptr = xc + (size_t)b * SEQL * DINNER + d;
    const float* zptr = xz + (size_t)b * SEQL * (2 * DINNER) + DINNER + d;
    const float* bcb  = bc + (size_t)b * SEQL * 32;
    float*       gptr = g  + (size_t)b * SEQL * DINNER + d;

    float h = 0.f;
    for (int l = 0; l < SEQL; l++) {
        float dtv = dptr[(size_t)l * DINNER];
        float xt  = xptr[(size_t)l * DINNER];
        float Bt  = bcb[l * 32 + s];
        float Ct  = bcb[l * 32 + 16 + s];

        float dA = expf(dtv * a);
        h = fmaf(dA, h, dtv * xt * Bt);

        float p = h * Ct;
        p += __shfl_xor_sync(0xffffffffu, p, 8);
        p += __shfl_xor_sync(0xffffffffu, p, 4);
        p += __shfl_xor_sync(0xffffffffu, p, 2);
        p += __shfl_xor_sync(0xffffffffu, p, 1);

        if (s == 0) {
            float y   = fmaf(Dd, xt, p);
            float z   = zptr[(size_t)l * (2 * DINNER)];
            float sig = 1.f / (1.f + expf(-z));
            gptr[(size_t)l * DINNER] = y * (z * sig);
        }
    }
}

// ---------------- launch ----------------
extern "C" void kernel_launch(void* const* d_in, const int* in_sizes, int n_in,
                              void* d_out, int out_size)
{
    const float* x      = (const float*)d_in[0];   // [2,2048,1024]
    const float* W_in   = (const float*)d_in[1];   // [1024,4096]
    const float* conv_w = (const float*)d_in[2];   // [2048,4]
    const float* conv_b = (const float*)d_in[3];   // [2048]
    const float* W_xprj = (const float*)d_in[4];   // [2048,32]
    const float* W_dt   = (const float*)d_in[5];   // [16,2048]
    const float* b_dt   = (const float*)d_in[6];   // [2048]
    const float* A_log  = (const float*)d_in[7];   // [2048,16]
    const float* Dvec   = (const float*)d_in[8];   // [2048]
    const float* W_out  = (const float*)d_in[9];   // [2048,1024]
    float* out = (float*)d_out;                    // [2,2048,1024]

    float *xz, *xc, *bc, *dt, *gg;
    cudaGetSymbolAddress((void**)&xz, g_xz);
    cudaGetSymbolAddress((void**)&xc, g_xc);
    cudaGetSymbolAddress((void**)&bc, g_bc);
    cudaGetSymbolAddress((void**)&dt, g_dt);
    cudaGetSymbolAddress((void**)&gg, g_gg);

    // 1) xz = x @ W_in     (M=4096, K=1024, N=4096)
    {
        dim3 grid(2 * DINNER / TBN, NROWS / TBM);
        tf32gemm_kernel<<<grid, 256>>>(x, W_in, xz, NROWS, 2 * DINNER, DMODEL);
    }
    // 2) depthwise conv + SiLU
    {
        int total = NROWS * DINNER;
        conv_silu_kernel<<<(total + 255) / 256, 256>>>(xz, conv_w, conv_b, xc);
    }
    // 3) BC = xc @ W_xproj
    xproj_kernel<<<NROWS, 256>>>(xc, W_xprj, bc);
    // 4) delta = softplus(B @ W_dt + b_dt)
    {
        int total = NROWS * DINNER;
        delta_kernel<<<(total + 255) / 256, 256>>>(bc, W_dt, b_dt, dt);
    }
    // 5) selective scan + gate fusion
    {
        int total = BATCH * DINNER * DSTATE;   // 65536
        scan_kernel<<<total / 256, 256>>>(xc, dt, bc, A_log, Dvec, xz, gg);
    }
    // 6) out = g @ W_out   (M=4096, K=2048, N=1024)
    {
        dim3 grid(DMODEL / TBN, NROWS / TBM);
        tf32gemm_kernel<<<grid, 256>>>(gg, W_out, out, NROWS, DMODEL, DINNER);
    }
}